// round 16
// baseline (speedup 1.0000x reference)
#include <cuda_runtime.h>
#include <cuda_fp16.h>
#include <cstdint>

#define BB 4
#define LL 2048
#define KK 48
#define HH 128
#define FFD 512
#define NN (BB*LL)          /* 8192 nodes */
#define NPB 2               /* nodes per block in msg kernels */
#define ROWS (NPB*KK)       /* 96 rows */
#define MSG_THREADS 384     /* 12 warps: 3 m-groups x 4 n-groups */

/* msg smem layout (strides % 128B == 16B -> conflict-free ldmatrix) */
#define ASM_LD 136
#define TSM_LD 136
#define WSM_LD 136
#define ROW_B 272
#define OFF_GBE 26112
#define OFF_P2  27648
#define OFF_TSM 33792
#define OFF_WSM 59904
#define OFF_S1S 94720
#define OFF_B2  95744
#define OFF_MSK 96256
#define SMEM_BYTES 96640

/* ffn smem layout (R14: 64 nodes/block) */
#define FFN_OFF_V 0
#define FFN_OFF_F 17408
#define FFN_OFF_W 34816
#define FFN_OFF_C 69632
#define FFN_CLD 132
#define FFN_SMEM 103424

/* prep kernel block ranges */
#define PREP_E_BLOCKS 24576
#define PREP_W_BLOCKS 576
#define PREP_S_BLOCKS 256
#define PREP_GRID (PREP_E_BLOCKS + PREP_W_BLOCKS + PREP_S_BLOCKS)

// ---------------- device scratch (no allocation allowed) ----------------
__device__ __half g_W1h[384*HH];
__device__ __half g_W2h[HH*HH];
__device__ __half g_W3h[HH*HH];
__device__ __half g_W11h[384*HH];
__device__ __half g_W12h[HH*HH];
__device__ __half g_W13h[HH*HH];
__device__ __half g_Winh[HH*FFD];
__device__ __half g_Wouth[FFD*HH];
__device__ __half g_hEh[NN*KK*HH];    // fp16 of h_E
__device__ float  g_dh[NN*HH];        // node-message sums
__device__ float  g_S1[NN*HH];        // hv @ W1a + b1  (fp32)
__device__ __half g_T3h[NN*HH];       // hv @ W1c       (fp16, gathered)
__device__ float  g_vln[NN*HH];       // fp32 LN1 output (ffn residual)

// fast gelu: tanh-form with HW tanh.approx
__device__ __forceinline__ float gelu_f(float x) {
    float x2 = x * x;
    float u = 0.7978845608028654f * fmaf(0.044715f * x2, x, x);
    float t;
    asm("tanh.approx.f32 %0, %1;" : "=f"(t) : "f"(u));
    return 0.5f * x * (1.0f + t);
}

__device__ __forceinline__ float warp_sum(float x) {
    #pragma unroll
    for (int off = 16; off; off >>= 1) x += __shfl_xor_sync(0xffffffffu, x, off);
    return x;
}

// 16B async copy global -> shared
__device__ __forceinline__ void cp16(void* dst_smem, const void* src) {
    unsigned int d = (unsigned int)__cvta_generic_to_shared(dst_smem);
    asm volatile("cp.async.cg.shared.global [%0], [%1], 16;\n" :: "r"(d), "l"(src));
}
__device__ __forceinline__ void cp_commit_wait_all() {
    asm volatile("cp.async.commit_group;\n");
    asm volatile("cp.async.wait_group 0;\n");
}

// ---------------- mma.sync primitives ----------------
__device__ __forceinline__ void ldmA4(uint32_t a[4], unsigned ad) {
    asm volatile("ldmatrix.sync.aligned.m8n8.x4.shared.b16 {%0,%1,%2,%3}, [%4];"
                 : "=r"(a[0]),"=r"(a[1]),"=r"(a[2]),"=r"(a[3]) : "r"(ad));
}
__device__ __forceinline__ void ldmB4(uint32_t b[4], unsigned ad) {
    asm volatile("ldmatrix.sync.aligned.m8n8.x4.trans.shared.b16 {%0,%1,%2,%3}, [%4];"
                 : "=r"(b[0]),"=r"(b[1]),"=r"(b[2]),"=r"(b[3]) : "r"(ad));
}
__device__ __forceinline__ void mma16816(float c[4], const uint32_t a[4], const uint32_t b[2]) {
    asm volatile("mma.sync.aligned.m16n8k16.row.col.f32.f16.f16.f32 "
                 "{%0,%1,%2,%3}, {%4,%5,%6,%7}, {%8,%9}, {%0,%1,%2,%3};"
                 : "+f"(c[0]),"+f"(c[1]),"+f"(c[2]),"+f"(c[3])
                 : "r"(a[0]),"r"(a[1]),"r"(a[2]),"r"(a[3]), "r"(b[0]),"r"(b[1]));
}

// warp tile 32x32: acc[mi][nj][4]
__device__ __forceinline__ void gemm_tile(float acc[2][4][4], unsigned aBase, unsigned bBase) {
    #pragma unroll
    for (int ks = 0; ks < 8; ks++) {
        uint32_t af[2][4];
        ldmA4(af[0], aBase + ks*32);
        ldmA4(af[1], aBase + 16*ROW_B + ks*32);
        uint32_t bfx[8];
        ldmB4(&bfx[0], bBase + ks*16*ROW_B);        // j0, j1
        ldmB4(&bfx[4], bBase + ks*16*ROW_B + 32);   // j2, j3
        #pragma unroll
        for (int mi = 0; mi < 2; mi++)
            #pragma unroll
            for (int j = 0; j < 4; j++)
                mma16816(acc[mi][j], af[mi], &bfx[2*j]);
    }
}
__device__ __forceinline__ void zero_acc(float acc[2][4][4]) {
    #pragma unroll
    for (int mi = 0; mi < 2; mi++)
        #pragma unroll
        for (int j = 0; j < 4; j++)
            #pragma unroll
            for (int e = 0; e < 4; e++) acc[mi][j][e] = 0.0f;
}

// ---------------- S1/T3 device body (512 thr = 4 groups x 8 nodes) ----------------
__device__ __forceinline__ void s1t3_body(const float* __restrict__ hv,
                                          const float* __restrict__ W,
                                          const float* __restrict__ b,
                                          float* __restrict__ s1,
                                          __half* __restrict__ t3h,
                                          int n0base, float (*hvs)[HH]) {
    const int tid = threadIdx.x;
    for (int i = tid; i < 32*HH; i += 512)
        hvs[i >> 7][i & 127] = hv[(size_t)n0base*HH + i];
    __syncthreads();
    const int grp = tid >> 7, t = tid & 127;
    const int n0 = n0base + grp*8;
    float (*ghv)[HH] = hvs + grp*8;
    float acc1[8], acc3[8];
    float bb = b[t];
    #pragma unroll
    for (int a = 0; a < 8; a++) { acc1[a] = bb; acc3[a] = 0.0f; }
    const float* Wa = W + t;              // rows 0..127
    const float* Wc = W + 256*HH + t;     // rows 256..383
    #pragma unroll 4
    for (int i = 0; i < HH; i++) {
        float wa = Wa[i*HH];
        float wc = Wc[i*HH];
        #pragma unroll
        for (int a = 0; a < 8; a++) {
            float h = ghv[a][i];
            acc1[a] += h * wa;
            acc3[a] += h * wc;
        }
    }
    #pragma unroll
    for (int a = 0; a < 8; a++) {
        s1[(size_t)(n0 + a)*HH + t]  = acc1[a];
        t3h[(size_t)(n0 + a)*HH + t] = __float2half(acc3[a]);
    }
}

// ---------------- prep: convert_e U convert_w U s1t3(first) ----------------
__global__ __launch_bounds__(512)
void prep_kernel(const float* __restrict__ hE,
                 const float* __restrict__ W1, const float* __restrict__ W2,
                 const float* __restrict__ W3, const float* __restrict__ W11,
                 const float* __restrict__ W12, const float* __restrict__ W13,
                 const float* __restrict__ Win, const float* __restrict__ Wout,
                 const float* __restrict__ hV, const float* __restrict__ b1,
                 float* __restrict__ s1, __half* __restrict__ t3h) {
    __shared__ float hvs[32][HH];
    int blk = blockIdx.x;
    if (blk < PREP_E_BLOCKS) {
        int i = blk*512 + threadIdx.x;   // one float4
        float4 v = *(const float4*)(hE + (size_t)i*4);
        __half2* dst = (__half2*)(g_hEh + (size_t)i*4);
        dst[0] = __floats2half2_rn(v.x, v.y);
        dst[1] = __floats2half2_rn(v.z, v.w);
        return;
    }
    blk -= PREP_E_BLOCKS;
    if (blk < PREP_W_BLOCKS) {
        int i = blk*512 + threadIdx.x;
        if (i < 49152) { g_W1h[i]  = __float2half(W1[i]);  return; } i -= 49152;
        if (i < 16384) { g_W2h[i]  = __float2half(W2[i]);  return; } i -= 16384;
        if (i < 16384) { g_W3h[i]  = __float2half(W3[i]);  return; } i -= 16384;
        if (i < 49152) { g_W11h[i] = __float2half(W11[i]); return; } i -= 49152;
        if (i < 16384) { g_W12h[i] = __float2half(W12[i]); return; } i -= 16384;
        if (i < 16384) { g_W13h[i] = __float2half(W13[i]); return; } i -= 16384;
        if (i < 65536) { g_Winh[i] = __float2half(Win[i]); return; } i -= 65536;
        if (i < 65536) { g_Wouth[i]= __float2half(Wout[i]); }
        return;
    }
    blk -= PREP_W_BLOCKS;
    s1t3_body(hV, W1, b1, s1, t3h, blk*32, hvs);
}

// ---------------- standalone s1t3 (second pass) ----------------
__global__ __launch_bounds__(512)
void s1t3_kernel(const float* __restrict__ hv, const float* __restrict__ W,
                 const float* __restrict__ b,
                 float* __restrict__ s1, __half* __restrict__ t3h) {
    __shared__ float hvs[32][HH];
    s1t3_body(hv, W, b, s1, t3h, blockIdx.x*32, hvs);
}

// ---------------- K1 / K3: fused 3-layer message MLP ----------------
template<bool NODE>
__global__ __launch_bounds__(MSG_THREADS, 2)
void msg_kernel(const __half* __restrict__ hEh,       // fp16 h_E (A operand + residual)
                const float* __restrict__ S1g,
                const __half* __restrict__ T3h,
                const __half* __restrict__ Wbch,      // fp16 [384,128]; rows 128..255 used
                const __half* __restrict__ W2h,
                const __half* __restrict__ W3h,       // fp16 W3 (GEMM3 / matvec)
                const float* __restrict__ b2,
                const float* __restrict__ b3,
                const int*   __restrict__ E_idx,
                const float* __restrict__ mask_attend,
                const float* __restrict__ g3,
                const float* __restrict__ be3,
                float* __restrict__ out)
{
    extern __shared__ char smem[];
    __half* Asm = (__half*)smem;                 // [96][136]
    float*  GBEs = (float*)(smem + OFF_GBE);     // g3|be3|b3
    __half* Tsm = (__half*)(smem + OFF_TSM);     // [96][136] (T3 phase0 -> activations)
    __half* Wsm = (__half*)(smem + OFF_WSM);     // [128][136]
    float*  S1s = (float*)(smem + OFF_S1S);
    float*  B2s = (float*)(smem + OFF_B2);
    float*  MSKs = (float*)(smem + OFF_MSK);

    const int tid = threadIdx.x;
    const int node0 = blockIdx.x * NPB;
    const int w  = tid >> 5;
    const int lane = tid & 31;
    const int wm = w % 3, wn = w / 3;            // 3 m-groups x 4 n-groups
    const int g = lane >> 2, q = lane & 3;

    // ---- phase0: async hE tile + T3 gather + W1b + S1/b2/mask/GBE ----
    for (int idx = tid; idx < ROWS*16; idx += MSG_THREADS) {
        int r = idx >> 4, s = idx & 15;
        int nl = (r >= 48), k = r - nl*48;
        size_t e = (size_t)((node0 + nl)*KK + k);
        cp16(Asm + r*ASM_LD + s*8, hEh + e*HH + s*8);
    }
    for (int idx = tid; idx < ROWS*16; idx += MSG_THREADS) {
        int r = idx >> 4, s = idx & 15;
        int nl = (r >= 48), k = r - nl*48;
        int n  = node0 + nl;
        int nbr = (n & ~(LL-1)) + E_idx[n*KK + k];   // b*L + idx
        cp16(Tsm + r*TSM_LD + s*8, T3h + (size_t)nbr*HH + s*8);
    }
    for (int idx = tid; idx < 2048; idx += MSG_THREADS) {
        int row = idx >> 4, c = idx & 15;
        cp16(Wsm + row*WSM_LD + c*8, Wbch + (128 + row)*HH + c*8);
    }
    if (tid < 2*HH) S1s[tid] = S1g[(size_t)node0*HH + tid];
    else            B2s[tid - 256] = b2[tid - 256];
    GBEs[tid] = (tid < 128) ? g3[tid] : (tid < 256 ? be3[tid-128] : b3[tid-256]);
    if (NODE && tid < ROWS) MSKs[tid] = mask_attend[node0*KK + tid];
    cp_commit_wait_all();
    __syncthreads();

    const unsigned aOff = (unsigned)((wm*32 + (lane & 15)) * ROW_B + ((lane >> 4) << 4));
    const unsigned aBaseE = (unsigned)__cvta_generic_to_shared(Asm) + aOff;
    const unsigned aBaseT = (unsigned)__cvta_generic_to_shared(Tsm) + aOff;
    const unsigned bBase  = (unsigned)__cvta_generic_to_shared(Wsm)
                          + (unsigned)((lane & 15) * ROW_B + wn*64 + ((lane >> 4) << 4));

    float acc[2][4][4];

    // ---- GEMM1: hE[96,128] @ W1b ----
    zero_acc(acc);
    gemm_tile(acc, aBaseE, bBase);
    __syncthreads();                    // Wsm reads done before restage

    // ---- epilogue1 (+S1 +T3) + stage W2 ----
    for (int idx = tid; idx < 2048; idx += MSG_THREADS) {
        int row = idx >> 4, c = idx & 15;
        cp16(Wsm + row*WSM_LD + c*8, W2h + row*HH + c*8);
    }
    #pragma unroll
    for (int mi = 0; mi < 2; mi++) {
        int rb = wm*32 + mi*16 + g;
        #pragma unroll
        for (int j = 0; j < 4; j++) {
            int h0 = wn*32 + j*8 + q*2;
            #pragma unroll
            for (int s = 0; s < 2; s++) {
                int r = rb + s*8;
                float2 s1 = *(const float2*)(S1s + (r >= 48 ? HH : 0) + h0);
                float2 t3 = __half22float2(*(const __half2*)(Tsm + r*TSM_LD + h0));
                float v0 = gelu_f(acc[mi][j][2*s]   + s1.x + t3.x);
                float v1 = gelu_f(acc[mi][j][2*s+1] + s1.y + t3.y);
                *(__half2*)(Tsm + r*TSM_LD + h0) = __floats2half2_rn(v0, v1);
            }
        }
    }
    cp_commit_wait_all();
    __syncthreads();

    // ---- GEMM2 ----
    zero_acc(acc);
    gemm_tile(acc, aBaseT, bBase);
    __syncthreads();                    // Tsm + Wsm reads done

    // ---- epilogue2 (+b2) + stage W3 ----
    for (int idx = tid; idx < 2048; idx += MSG_THREADS) {
        int row = idx >> 4, c = idx & 15;
        cp16(Wsm + row*WSM_LD + c*8, W3h + row*HH + c*8);
    }

    if (NODE) {
        // masked rowsum computed entirely in registers, no Act2 write
        float* P = (float*)(smem + OFF_P2);             // [6][128]
        #pragma unroll
        for (int mi = 0; mi < 2; mi++) {
            int r0 = wm*32 + mi*16 + g;
            float m0 = MSKs[r0], m1 = MSKs[r0 + 8];
            #pragma unroll
            for (int j = 0; j < 4; j++) {
                int h0 = wn*32 + j*8 + q*2;
                float2 bb = *(const float2*)(B2s + h0);
                float t0 = m0*gelu_f(acc[mi][j][0] + bb.x) + m1*gelu_f(acc[mi][j][2] + bb.x);
                float t1 = m0*gelu_f(acc[mi][j][1] + bb.y) + m1*gelu_f(acc[mi][j][3] + bb.y);
                #pragma unroll
                for (int off = 4; off <= 16; off <<= 1) {
                    t0 += __shfl_xor_sync(0xffffffffu, t0, off);
                    t1 += __shfl_xor_sync(0xffffffffu, t1, off);
                }
                if (g == 0) {
                    int band = wm*2 + mi;               // 16-row band, single node
                    *(float2*)(P + band*128 + h0) = make_float2(t0, t1);
                }
            }
        }
        cp_commit_wait_all();
        __syncthreads();
        // combine bands -> msum[2][128]
        float* msum = (float*)(smem + OFF_P2 + 3072);
        if (tid < 2*HH) {
            int nl2 = tid >> 7, h = tid & 127;
            msum[nl2*HH + h] = P[(nl2*3 + 0)*128 + h] + P[(nl2*3 + 1)*128 + h]
                             + P[(nl2*3 + 2)*128 + h];
        }
        __syncthreads();
        // fp32-accum matvec from smem fp16 W3 (4-way ILP) + smk*b3
        if (tid < 2*HH) {
            int nl2 = tid >> 7, h = tid & 127;
            float smk = 0.0f;
            #pragma unroll 8
            for (int k = 0; k < KK; k++) smk += MSKs[nl2*48 + k];
            const float* mrow = msum + nl2*HH;
            float a0 = 0.0f, a1 = 0.0f, a2 = 0.0f, a3 = 0.0f;
            #pragma unroll 8
            for (int k = 0; k < HH; k += 4) {
                a0 += mrow[k]   * __half2float(Wsm[(k  )*WSM_LD + h]);
                a1 += mrow[k+1] * __half2float(Wsm[(k+1)*WSM_LD + h]);
                a2 += mrow[k+2] * __half2float(Wsm[(k+2)*WSM_LD + h]);
                a3 += mrow[k+3] * __half2float(Wsm[(k+3)*WSM_LD + h]);
            }
            float a = smk * GBEs[256 + h] + ((a0 + a1) + (a2 + a3));
            out[(size_t)(node0 + nl2)*HH + h] = a * (1.0f/30.0f);
        }
    } else {
        #pragma unroll
        for (int mi = 0; mi < 2; mi++) {
            int rb = wm*32 + mi*16 + g;
            #pragma unroll
            for (int j = 0; j < 4; j++) {
                int h0 = wn*32 + j*8 + q*2;
                float2 bb = *(const float2*)(B2s + h0);
                #pragma unroll
                for (int s = 0; s < 2; s++) {
                    int r = rb + s*8;
                    float v0 = gelu_f(acc[mi][j][2*s]   + bb.x);
                    float v1 = gelu_f(acc[mi][j][2*s+1] + bb.y);
                    *(__half2*)(Tsm + r*TSM_LD + h0) = __floats2half2_rn(v0, v1);
                }
            }
        }
        cp_commit_wait_all();
        __syncthreads();

        // ---- GEMM3, then LN directly from accumulators (residual from Asm) ----
        zero_acc(acc);
        gemm_tile(acc, aBaseT, bBase);

        float2* P2 = (float2*)(smem + OFF_P2);   // [2][96][4]
        #pragma unroll
        for (int mi = 0; mi < 2; mi++) {
            int rb = wm*32 + mi*16 + g;
            #pragma unroll
            for (int s = 0; s < 2; s++) {
                int r = rb + s*8;
                float psum = 0.0f, psq = 0.0f;
                #pragma unroll
                for (int j = 0; j < 4; j++) {
                    int h0 = wn*32 + j*8 + q*2;
                    float2 he = __half22float2(*(const __half2*)(Asm + r*ASM_LD + h0));
                    float x0 = acc[mi][j][2*s]   + GBEs[256 + h0]     + he.x;
                    float x1 = acc[mi][j][2*s+1] + GBEs[256 + h0 + 1] + he.y;
                    acc[mi][j][2*s] = x0; acc[mi][j][2*s+1] = x1;
                    psum += x0 + x1;
                    psq  += x0*x0 + x1*x1;
                }
                psum += __shfl_xor_sync(0xffffffffu, psum, 1);
                psq  += __shfl_xor_sync(0xffffffffu, psq, 1);
                psum += __shfl_xor_sync(0xffffffffu, psum, 2);
                psq  += __shfl_xor_sync(0xffffffffu, psq, 2);
                if (q == 0) P2[mi*384 + r*4 + wn] = make_float2(psum, psq);
            }
        }
        __syncthreads();
        #pragma unroll
        for (int mi = 0; mi < 2; mi++) {
            int rb = wm*32 + mi*16 + g;
            #pragma unroll
            for (int s = 0; s < 2; s++) {
                int r = rb + s*8;
                int nl = (r >= 48), k = r - nl*48;
                size_t eoff = (size_t)((node0 + nl)*KK + k) * HH;
                float2 p0 = P2[mi*384 + r*4 + 0];
                float2 p1 = P2[mi*384 + r*4 + 1];
                float2 p2 = P2[mi*384 + r*4 + 2];
                float2 p3 = P2[mi*384 + r*4 + 3];
                float sum = p0.x + p1.x + p2.x + p3.x;
                float sq  = p0.y + p1.y + p2.y + p3.y;
                float m   = sum * (1.0f/128.0f);
                float var = sq * (1.0f/128.0f) - m*m;
                float rs  = rsqrtf(var + 1e-5f);
                #pragma unroll
                for (int j = 0; j < 4; j++) {
                    int h0 = wn*32 + j*8 + q*2;
                    float o0 = (acc[mi][j][2*s]   - m)*rs*GBEs[h0]     + GBEs[128 + h0];
                    float o1 = (acc[mi][j][2*s+1] - m)*rs*GBEs[h0 + 1] + GBEs[128 + h0 + 1];
                    *(float2*)(out + eoff + h0) = make_float2(o0, o1);
                }
            }
        }
    }
}

// ---------------- K2: LN1 + FFN (wmma, 64 nodes/block — R14) ----------------
#include <mma.h>
using namespace nvcuda;
using FragA = wmma::fragment<wmma::matrix_a, 16,16,16, __half, wmma::row_major>;
using FragB = wmma::fragment<wmma::matrix_b, 16,16,16, __half, wmma::row_major>;
using FragC = wmma::fragment<wmma::accumulator, 16,16,16, float>;

__global__ __launch_bounds__(256, 2)
void ffn_wmma_kernel(const float* __restrict__ hV, const float* __restrict__ dh,
                     const float* __restrict__ g1, const float* __restrict__ be1,
                     const float* __restrict__ g2, const float* __restrict__ be2,
                     const __half* __restrict__ Winh, const float* __restrict__ binf,
                     const __half* __restrict__ Wouth, const float* __restrict__ bout,
                     const float* __restrict__ mask_V, float* __restrict__ vln,
                     float* __restrict__ outV)
{
    extern __shared__ char smem[];
    __half* Vh  = (__half*)(smem + FFN_OFF_V);
    __half* Fsm = (__half*)(smem + FFN_OFF_F);
    __half* Wsm = (__half*)(smem + FFN_OFF_W);
    float*  Csm = (float*)(smem + FFN_OFF_C);

    const int tid = threadIdx.x;
    const int node0 = blockIdx.x * 64;
    const int wp = tid >> 5, lane = tid & 31;
    const int wm = wp & 3, wn = wp >> 2;

    for (int i = 0; i < 8; i++) {
        int nl = wp*8 + i, n = node0 + nl;
        float u[4]; float m = 0.0f;
        #pragma unroll
        for (int q = 0; q < 4; q++) {
            int h = lane + 32*q;
            u[q] = hV[(size_t)n*HH + h] + dh[(size_t)n*HH + h];
            m += u[q];
        }
        m = warp_sum(m) * (1.0f/128.0f);
        float var = 0.0f;
        #pragma unroll
        for (int q = 0; q < 4; q++) { float d = u[q]-m; var += d*d; }
        var = warp_sum(var) * (1.0f/128.0f);
        float rs = rsqrtf(var + 1e-5f);
        #pragma unroll
        for (int q = 0; q < 4; q++) {
            int h = lane + 32*q;
            float vl = (u[q]-m)*rs*g1[h] + be1[h];
            Vh[nl*136 + h] = __float2half(vl);
            vln[(size_t)n*HH + h] = vl;
        }
    }
    __syncthreads();

    FragC acc2[4];
    #pragma unroll
    for (int j = 0; j < 4; j++) wmma::fill_fragment(acc2[j], 0.0f);

    for (int jc = 0; jc < 4; jc++) {
        for (int idx = tid; idx < 2048; idx += 256) {
            int row = idx >> 4, c = idx & 15;
            cp16(Wsm + row*136 + c*8, Winh + (size_t)row*FFD + jc*128 + c*8);
        }
        cp_commit_wait_all();
        __syncthreads();
        FragC acc1[4];
        #pragma unroll
        for (int j = 0; j < 4; j++) wmma::fill_fragment(acc1[j], 0.0f);
        #pragma unroll
        for (int ks = 0; ks < 8; ks++) {
            FragA fa;
            wmma::load_matrix_sync(fa, Vh + (wm*16)*136 + ks*16, 136);
            #pragma unroll
            for (int j = 0; j < 4; j++) {
                FragB fb;
                wmma::load_matrix_sync(fb, Wsm + (ks*16)*136 + wn*64 + j*16, 136);
                wmma::mma_sync(acc1[j], fa, fb, acc1[j]);
            }
        }
        #pragma unroll
        for (int j = 0; j < 4; j++)
            wmma::store_matrix_sync(Csm + (wm*16)*FFN_CLD + wn*64 + j*16,
                                    acc1[j], FFN_CLD, wmma::mem_row_major);
        __syncthreads();
        for (int idx = tid; idx < 2048; idx += 256) {
            int row = idx >> 4, c = idx & 15;
            cp16(Wsm + row*136 + c*8, Wouth + (size_t)(jc*128 + row)*HH + c*8);
        }
        for (int idx = tid; idx < 64*128; idx += 256) {
            int r = idx >> 7, h = idx & 127;
            Fsm[r*136 + h] = __float2half(gelu_f(Csm[r*FFN_CLD + h] + binf[jc*128 + h]));
        }
        cp_commit_wait_all();
        __syncthreads();
        #pragma unroll
        for (int ks = 0; ks < 8; ks++) {
            FragA fa;
            wmma::load_matrix_sync(fa, Fsm + (wm*16)*136 + ks*16, 136);
            #pragma unroll
            for (int j = 0; j < 4; j++) {
                FragB fb;
                wmma::load_matrix_sync(fb, Wsm + (ks*16)*136 + wn*64 + j*16, 136);
                wmma::mma_sync(acc2[j], fa, fb, acc2[j]);
            }
        }
        __syncthreads();
    }
    #pragma unroll
    for (int j = 0; j < 4; j++)
        wmma::store_matrix_sync(Csm + (wm*16)*FFN_CLD + wn*64 + j*16,
                                acc2[j], FFN_CLD, wmma::mem_row_major);
    __syncthreads();

    for (int i = 0; i < 8; i++) {
        int nl = wp*8 + i, n = node0 + nl;
        float x[4]; float m = 0.0f;
        #pragma unroll
        for (int q = 0; q < 4; q++) {
            int h = lane + 32*q;
            x[q] = vln[(size_t)n*HH + h] + Csm[nl*FFN_CLD + h] + bout[h];
            m += x[q];
        }
        m = warp_sum(m) * (1.0f/128.0f);
        float var = 0.0f;
        #pragma unroll
        for (int q = 0; q < 4; q++) { float d = x[q]-m; var += d*d; }
        var = warp_sum(var) * (1.0f/128.0f);
        float rs = rsqrtf(var + 1e-5f);
        float mv = mask_V[n];
        #pragma unroll
        for (int q = 0; q < 4; q++) {
            int h = lane + 32*q;
            float o = ((x[q]-m)*rs*g2[h] + be2[h]) * mv;
            outV[(size_t)n*HH + h]  = o;
        }
    }
}

// ---------------- host ----------------
extern "C" void kernel_launch(void* const* d_in, const int* in_sizes, int n_in,
                              void* d_out, int out_size) {
    const float* h_V      = (const float*)d_in[0];
    const float* h_E      = (const float*)d_in[1];
    const float* mask_V   = (const float*)d_in[2];
    const float* mask_att = (const float*)d_in[3];
    const float* W1   = (const float*)d_in[4];
    const float* b1   = (const float*)d_in[5];
    const float* W2   = (const float*)d_in[6];
    const float* b2   = (const float*)d_in[7];
    const float* W3   = (const float*)d_in[8];
    const float* b3   = (const float*)d_in[9];
    const float* W11  = (const float*)d_in[10];
    const float* b11  = (const float*)d_in[11];
    const float* W12  = (const float*)d_in[12];
    const float* b12  = (const float*)d_in[13];
    const float* W13  = (const float*)d_in[14];
    const float* b13  = (const float*)d_in[15];
    const float* Win  = (const float*)d_in[16];
    const float* binf = (const float*)d_in[17];
    const float* Wout = (const float*)d_in[18];
    const float* bout = (const float*)d_in[19];
    const float* g1   = (const float*)d_in[20];
    const float* be1  = (const float*)d_in[21];
    const float* g2   = (const float*)d_in[22];
    const float* be2  = (const float*)d_in[23];
    const float* g3   = (const float*)d_in[24];
    const float* be3  = (const float*)d_in[25];
    const int*   E_idx = (const int*)d_in[26];

    float* outV = (float*)d_out;
    float* outE = outV + (size_t)NN*HH;

    cudaFuncSetAttribute(msg_kernel<true>,  cudaFuncAttributeMaxDynamicSharedMemorySize, SMEM_BYTES);
    cudaFuncSetAttribute(msg_kernel<false>, cudaFuncAttributeMaxDynamicSharedMemorySize, SMEM_BYTES);
    cudaFuncSetAttribute(ffn_wmma_kernel,   cudaFuncAttributeMaxDynamicSharedMemorySize, FFN_SMEM);

    __half *W1h, *W2h, *W3h, *W11h, *W12h, *W13h, *Winh, *Wouth, *hEh, *T3hp;
    float *dhp, *S1p, *vlnp;
    cudaGetSymbolAddress((void**)&W1h,  g_W1h);
    cudaGetSymbolAddress((void**)&W2h,  g_W2h);
    cudaGetSymbolAddress((void**)&W3h,  g_W3h);
    cudaGetSymbolAddress((void**)&W11h, g_W11h);
    cudaGetSymbolAddress((void**)&W12h, g_W12h);
    cudaGetSymbolAddress((void**)&W13h, g_W13h);
    cudaGetSymbolAddress((void**)&Winh, g_Winh);
    cudaGetSymbolAddress((void**)&Wouth,g_Wouth);
    cudaGetSymbolAddress((void**)&hEh,  g_hEh);
    cudaGetSymbolAddress((void**)&T3hp, g_T3h);
    cudaGetSymbolAddress((void**)&dhp,  g_dh);
    cudaGetSymbolAddress((void**)&S1p,  g_S1);
    cudaGetSymbolAddress((void**)&vlnp, g_vln);

    prep_kernel<<<PREP_GRID, 512>>>(h_E, W1, W2, W3, W11, W12, W13, Win, Wout,
                                    h_V, b1, S1p, T3hp);

    msg_kernel<true><<<NN/NPB, MSG_THREADS, SMEM_BYTES>>>(
        hEh, S1p, T3hp, W1h, W2h, W3h, b2, b3,
        E_idx, mask_att, g1, be1, dhp);

    ffn_wmma_kernel<<<NN/64, 256, FFN_SMEM>>>(h_V, dhp, g1, be1, g2, be2,
                                              Winh, binf, Wouth, bout, mask_V,
                                              vlnp, outV);

    s1t3_kernel<<<NN/32, 512>>>(outV, W11, b11, S1p, T3hp);

    msg_kernel<false><<<NN/NPB, MSG_THREADS, SMEM_BYTES>>>(
        hEh, S1p, T3hp, W11h, W12h, W13h, b12, b13,
        E_idx, nullptr, g3, be3, outE);
}

// round 17
// speedup vs baseline: 1.0568x; 1.0568x over previous
#include <cuda_runtime.h>
#include <cuda_fp16.h>
#include <cstdint>

#define BB 4
#define LL 2048
#define KK 48
#define HH 128
#define FFD 512
#define NN (BB*LL)          /* 8192 nodes */
#define NPB 2               /* nodes per block in msg kernels */
#define ROWS (NPB*KK)       /* 96 rows */
#define MSG_THREADS 384     /* 12 warps: 3 m-groups x 4 n-groups */

/* msg smem layout (strides % 128B == 16B -> conflict-free ldmatrix) */
#define ASM_LD 136
#define TSM_LD 136
#define WSM_LD 136
#define ROW_B 272
#define OFF_GBE 26112
#define OFF_P2  27648
#define OFF_TSM 33792
#define OFF_WSM 59904
#define OFF_S1S 94720
#define OFF_B2  95744
#define OFF_MSK 96256
#define SMEM_BYTES 96640

/* ffn smem layout (64 nodes/block) */
#define FFN_OFF_V 0
#define FFN_OFF_F 17408
#define FFN_OFF_W 34816
#define FFN_OFF_C 69632
#define FFN_CLD 132
#define FFN_SMEM 103424

/* conversion kernel block split (512 threads each) */
#define CV_E_BLOCKS 24576
#define CV_W_BLOCKS 576
#define CV_GRID (CV_E_BLOCKS + CV_W_BLOCKS)

// ---------------- device scratch (no allocation allowed) ----------------
__device__ __half g_W1h[384*HH];
__device__ __half g_W2h[HH*HH];
__device__ __half g_W3h[HH*HH];
__device__ __half g_W11h[384*HH];
__device__ __half g_W12h[HH*HH];
__device__ __half g_W13h[HH*HH];
__device__ __half g_Winh[HH*FFD];
__device__ __half g_Wouth[FFD*HH];
__device__ __half g_hEh[NN*KK*HH];    // fp16 of h_E
__device__ float  g_dh[NN*HH];        // node-message sums
__device__ float  g_S1[NN*HH];        // hv @ W1a + b1  (fp32)
__device__ __half g_T3h[NN*HH];       // hv @ W1c       (fp16, gathered)
__device__ float  g_vln[NN*HH];       // fp32 LN1 output (ffn residual)

// fast gelu: tanh-form with HW tanh.approx
__device__ __forceinline__ float gelu_f(float x) {
    float x2 = x * x;
    float u = 0.7978845608028654f * fmaf(0.044715f * x2, x, x);
    float t;
    asm("tanh.approx.f32 %0, %1;" : "=f"(t) : "f"(u));
    return 0.5f * x * (1.0f + t);
}

__device__ __forceinline__ float warp_sum(float x) {
    #pragma unroll
    for (int off = 16; off; off >>= 1) x += __shfl_xor_sync(0xffffffffu, x, off);
    return x;
}

// 16B async copy global -> shared
__device__ __forceinline__ void cp16(void* dst_smem, const void* src) {
    unsigned int d = (unsigned int)__cvta_generic_to_shared(dst_smem);
    asm volatile("cp.async.cg.shared.global [%0], [%1], 16;\n" :: "r"(d), "l"(src));
}
__device__ __forceinline__ void cp_commit_wait_all() {
    asm volatile("cp.async.commit_group;\n");
    asm volatile("cp.async.wait_group 0;\n");
}

// ---------------- mma.sync primitives ----------------
__device__ __forceinline__ void ldmA4(uint32_t a[4], unsigned ad) {
    asm volatile("ldmatrix.sync.aligned.m8n8.x4.shared.b16 {%0,%1,%2,%3}, [%4];"
                 : "=r"(a[0]),"=r"(a[1]),"=r"(a[2]),"=r"(a[3]) : "r"(ad));
}
__device__ __forceinline__ void ldmB4(uint32_t b[4], unsigned ad) {
    asm volatile("ldmatrix.sync.aligned.m8n8.x4.trans.shared.b16 {%0,%1,%2,%3}, [%4];"
                 : "=r"(b[0]),"=r"(b[1]),"=r"(b[2]),"=r"(b[3]) : "r"(ad));
}
__device__ __forceinline__ void mma16816(float c[4], const uint32_t a[4], const uint32_t b[2]) {
    asm volatile("mma.sync.aligned.m16n8k16.row.col.f32.f16.f16.f32 "
                 "{%0,%1,%2,%3}, {%4,%5,%6,%7}, {%8,%9}, {%0,%1,%2,%3};"
                 : "+f"(c[0]),"+f"(c[1]),"+f"(c[2]),"+f"(c[3])
                 : "r"(a[0]),"r"(a[1]),"r"(a[2]),"r"(a[3]), "r"(b[0]),"r"(b[1]));
}

// warp tile 32x32: acc[mi][nj][4]
__device__ __forceinline__ void gemm_tile(float acc[2][4][4], unsigned aBase, unsigned bBase) {
    #pragma unroll
    for (int ks = 0; ks < 8; ks++) {
        uint32_t af[2][4];
        ldmA4(af[0], aBase + ks*32);
        ldmA4(af[1], aBase + 16*ROW_B + ks*32);
        uint32_t bfx[8];
        ldmB4(&bfx[0], bBase + ks*16*ROW_B);        // j0, j1
        ldmB4(&bfx[4], bBase + ks*16*ROW_B + 32);   // j2, j3
        #pragma unroll
        for (int mi = 0; mi < 2; mi++)
            #pragma unroll
            for (int j = 0; j < 4; j++)
                mma16816(acc[mi][j], af[mi], &bfx[2*j]);
    }
}
__device__ __forceinline__ void zero_acc(float acc[2][4][4]) {
    #pragma unroll
    for (int mi = 0; mi < 2; mi++)
        #pragma unroll
        for (int j = 0; j < 4; j++)
            #pragma unroll
            for (int e = 0; e < 4; e++) acc[mi][j][e] = 0.0f;
}

// ---------------- K0: h_E + all weights fp32 -> fp16 (merged) ----------------
__global__ __launch_bounds__(512)
void convert_kernel(const float* __restrict__ hE,
                    const float* __restrict__ W1, const float* __restrict__ W2,
                    const float* __restrict__ W3, const float* __restrict__ W11,
                    const float* __restrict__ W12, const float* __restrict__ W13,
                    const float* __restrict__ Win, const float* __restrict__ Wout) {
    int blk = blockIdx.x;
    if (blk < CV_E_BLOCKS) {
        int i = blk*512 + threadIdx.x;   // one float4
        float4 v = *(const float4*)(hE + (size_t)i*4);
        __half2* dst = (__half2*)(g_hEh + (size_t)i*4);
        dst[0] = __floats2half2_rn(v.x, v.y);
        dst[1] = __floats2half2_rn(v.z, v.w);
        return;
    }
    int i = (blk - CV_E_BLOCKS)*512 + threadIdx.x;
    if (i < 49152) { g_W1h[i]  = __float2half(W1[i]);  return; } i -= 49152;
    if (i < 16384) { g_W2h[i]  = __float2half(W2[i]);  return; } i -= 16384;
    if (i < 16384) { g_W3h[i]  = __float2half(W3[i]);  return; } i -= 16384;
    if (i < 49152) { g_W11h[i] = __float2half(W11[i]); return; } i -= 49152;
    if (i < 16384) { g_W12h[i] = __float2half(W12[i]); return; } i -= 16384;
    if (i < 16384) { g_W13h[i] = __float2half(W13[i]); return; } i -= 16384;
    if (i < 65536) { g_Winh[i] = __float2half(Win[i]); return; } i -= 65536;
    if (i < 65536) { g_Wouth[i]= __float2half(Wout[i]); }
}

// ---------------- S1/T3 precompute (fp32 math; 128 thr / 8 nodes) ----------------
__global__ __launch_bounds__(128)
void s1t3_kernel(const float* __restrict__ hv, const float* __restrict__ W,
                 const float* __restrict__ b,
                 float* __restrict__ s1, __half* __restrict__ t3h) {
    __shared__ float hvs[8][HH];
    const int n0 = blockIdx.x * 8;
    const int tid = threadIdx.x;
    for (int i = tid; i < 8*HH; i += 128) hvs[i >> 7][i & 127] = hv[(size_t)n0*HH + i];
    __syncthreads();
    float acc1[8], acc3[8];
    float bb = b[tid];
    #pragma unroll
    for (int a = 0; a < 8; a++) { acc1[a] = bb; acc3[a] = 0.0f; }
    const float* Wa = W + tid;            // rows 0..127
    const float* Wc = W + 256*HH + tid;   // rows 256..383
    #pragma unroll 4
    for (int i = 0; i < HH; i++) {
        float wa = Wa[i*HH];
        float wc = Wc[i*HH];
        #pragma unroll
        for (int a = 0; a < 8; a++) {
            float h = hvs[a][i];
            acc1[a] += h * wa;
            acc3[a] += h * wc;
        }
    }
    #pragma unroll
    for (int a = 0; a < 8; a++) {
        s1[(size_t)(n0 + a)*HH + tid]  = acc1[a];
        t3h[(size_t)(n0 + a)*HH + tid] = __float2half(acc3[a]);
    }
}

// ---------------- K1 / K3: fused 3-layer message MLP ----------------
template<bool NODE>
__global__ __launch_bounds__(MSG_THREADS, 2)
void msg_kernel(const __half* __restrict__ hEh,       // fp16 h_E (A operand + residual)
                const float* __restrict__ S1g,
                const __half* __restrict__ T3h,
                const __half* __restrict__ Wbch,      // fp16 [384,128]; rows 128..255 used
                const __half* __restrict__ W2h,
                const __half* __restrict__ W3h,       // fp16 W3 (GEMM3 / matvec)
                const float* __restrict__ b2,
                const float* __restrict__ b3,
                const int*   __restrict__ E_idx,
                const float* __restrict__ mask_attend,
                const float* __restrict__ g3,
                const float* __restrict__ be3,
                float* __restrict__ out)
{
    extern __shared__ char smem[];
    __half* Asm = (__half*)smem;                 // [96][136]
    float*  GBEs = (float*)(smem + OFF_GBE);     // g3|be3|b3
    __half* Tsm = (__half*)(smem + OFF_TSM);     // [96][136] (T3 phase0 -> activations)
    __half* Wsm = (__half*)(smem + OFF_WSM);     // [128][136]
    float*  S1s = (float*)(smem + OFF_S1S);
    float*  B2s = (float*)(smem + OFF_B2);
    float*  MSKs = (float*)(smem + OFF_MSK);

    const int tid = threadIdx.x;
    const int node0 = blockIdx.x * NPB;
    const int w  = tid >> 5;
    const int lane = tid & 31;
    const int wm = w % 3, wn = w / 3;            // 3 m-groups x 4 n-groups
    const int g = lane >> 2, q = lane & 3;

    // ---- phase0: async hE tile + T3 gather + W1b + S1/b2/mask/GBE ----
    for (int idx = tid; idx < ROWS*16; idx += MSG_THREADS) {
        int r = idx >> 4, s = idx & 15;
        int nl = (r >= 48), k = r - nl*48;
        size_t e = (size_t)((node0 + nl)*KK + k);
        cp16(Asm + r*ASM_LD + s*8, hEh + e*HH + s*8);
    }
    for (int idx = tid; idx < ROWS*16; idx += MSG_THREADS) {
        int r = idx >> 4, s = idx & 15;
        int nl = (r >= 48), k = r - nl*48;
        int n  = node0 + nl;
        int nbr = (n & ~(LL-1)) + E_idx[n*KK + k];   // b*L + idx
        cp16(Tsm + r*TSM_LD + s*8, T3h + (size_t)nbr*HH + s*8);
    }
    for (int idx = tid; idx < 2048; idx += MSG_THREADS) {
        int row = idx >> 4, c = idx & 15;
        cp16(Wsm + row*WSM_LD + c*8, Wbch + (128 + row)*HH + c*8);
    }
    if (tid < 2*HH) S1s[tid] = S1g[(size_t)node0*HH + tid];
    else            B2s[tid - 256] = b2[tid - 256];
    GBEs[tid] = (tid < 128) ? g3[tid] : (tid < 256 ? be3[tid-128] : b3[tid-256]);
    if (NODE && tid < ROWS) MSKs[tid] = mask_attend[node0*KK + tid];
    cp_commit_wait_all();
    __syncthreads();

    const unsigned aOff = (unsigned)((wm*32 + (lane & 15)) * ROW_B + ((lane >> 4) << 4));
    const unsigned aBaseE = (unsigned)__cvta_generic_to_shared(Asm) + aOff;
    const unsigned aBaseT = (unsigned)__cvta_generic_to_shared(Tsm) + aOff;
    const unsigned bBase  = (unsigned)__cvta_generic_to_shared(Wsm)
                          + (unsigned)((lane & 15) * ROW_B + wn*64 + ((lane >> 4) << 4));

    float acc[2][4][4];

    // ---- GEMM1: hE[96,128] @ W1b ----
    zero_acc(acc);
    gemm_tile(acc, aBaseE, bBase);
    __syncthreads();                    // Wsm reads done before restage

    // ---- epilogue1 (+S1 +T3) + stage W2 ----
    for (int idx = tid; idx < 2048; idx += MSG_THREADS) {
        int row = idx >> 4, c = idx & 15;
        cp16(Wsm + row*WSM_LD + c*8, W2h + row*HH + c*8);
    }
    #pragma unroll
    for (int mi = 0; mi < 2; mi++) {
        int rb = wm*32 + mi*16 + g;
        #pragma unroll
        for (int j = 0; j < 4; j++) {
            int h0 = wn*32 + j*8 + q*2;
            #pragma unroll
            for (int s = 0; s < 2; s++) {
                int r = rb + s*8;
                float2 s1 = *(const float2*)(S1s + (r >= 48 ? HH : 0) + h0);
                float2 t3 = __half22float2(*(const __half2*)(Tsm + r*TSM_LD + h0));
                float v0 = gelu_f(acc[mi][j][2*s]   + s1.x + t3.x);
                float v1 = gelu_f(acc[mi][j][2*s+1] + s1.y + t3.y);
                *(__half2*)(Tsm + r*TSM_LD + h0) = __floats2half2_rn(v0, v1);
            }
        }
    }
    cp_commit_wait_all();
    __syncthreads();

    // ---- GEMM2 ----
    zero_acc(acc);
    gemm_tile(acc, aBaseT, bBase);
    __syncthreads();                    // Tsm + Wsm reads done

    // ---- epilogue2 (+b2) + stage W3 ----
    for (int idx = tid; idx < 2048; idx += MSG_THREADS) {
        int row = idx >> 4, c = idx & 15;
        cp16(Wsm + row*WSM_LD + c*8, W3h + row*HH + c*8);
    }

    if (NODE) {
        // masked rowsum computed entirely in registers, no Act2 write
        float* P = (float*)(smem + OFF_P2);             // [6][128]
        #pragma unroll
        for (int mi = 0; mi < 2; mi++) {
            int r0 = wm*32 + mi*16 + g;
            float m0 = MSKs[r0], m1 = MSKs[r0 + 8];
            #pragma unroll
            for (int j = 0; j < 4; j++) {
                int h0 = wn*32 + j*8 + q*2;
                float2 bb = *(const float2*)(B2s + h0);
                float t0 = m0*gelu_f(acc[mi][j][0] + bb.x) + m1*gelu_f(acc[mi][j][2] + bb.x);
                float t1 = m0*gelu_f(acc[mi][j][1] + bb.y) + m1*gelu_f(acc[mi][j][3] + bb.y);
                #pragma unroll
                for (int off = 4; off <= 16; off <<= 1) {
                    t0 += __shfl_xor_sync(0xffffffffu, t0, off);
                    t1 += __shfl_xor_sync(0xffffffffu, t1, off);
                }
                if (g == 0) {
                    int band = wm*2 + mi;               // 16-row band, single node
                    *(float2*)(P + band*128 + h0) = make_float2(t0, t1);
                }
            }
        }
        cp_commit_wait_all();
        __syncthreads();
        // combine bands -> msum[2][128]
        float* msum = (float*)(smem + OFF_P2 + 3072);
        if (tid < 2*HH) {
            int nl2 = tid >> 7, h = tid & 127;
            msum[nl2*HH + h] = P[(nl2*3 + 0)*128 + h] + P[(nl2*3 + 1)*128 + h]
                             + P[(nl2*3 + 2)*128 + h];
        }
        __syncthreads();
        // fp32-accum matvec from smem fp16 W3 (4-way ILP) + smk*b3
        if (tid < 2*HH) {
            int nl2 = tid >> 7, h = tid & 127;
            float smk = 0.0f;
            #pragma unroll 8
            for (int k = 0; k < KK; k++) smk += MSKs[nl2*48 + k];
            const float* mrow = msum + nl2*HH;
            float a0 = 0.0f, a1 = 0.0f, a2 = 0.0f, a3 = 0.0f;
            #pragma unroll 8
            for (int k = 0; k < HH; k += 4) {
                a0 += mrow[k]   * __half2float(Wsm[(k  )*WSM_LD + h]);
                a1 += mrow[k+1] * __half2float(Wsm[(k+1)*WSM_LD + h]);
                a2 += mrow[k+2] * __half2float(Wsm[(k+2)*WSM_LD + h]);
                a3 += mrow[k+3] * __half2float(Wsm[(k+3)*WSM_LD + h]);
            }
            float a = smk * GBEs[256 + h] + ((a0 + a1) + (a2 + a3));
            out[(size_t)(node0 + nl2)*HH + h] = a * (1.0f/30.0f);
        }
    } else {
        #pragma unroll
        for (int mi = 0; mi < 2; mi++) {
            int rb = wm*32 + mi*16 + g;
            #pragma unroll
            for (int j = 0; j < 4; j++) {
                int h0 = wn*32 + j*8 + q*2;
                float2 bb = *(const float2*)(B2s + h0);
                #pragma unroll
                for (int s = 0; s < 2; s++) {
                    int r = rb + s*8;
                    float v0 = gelu_f(acc[mi][j][2*s]   + bb.x);
                    float v1 = gelu_f(acc[mi][j][2*s+1] + bb.y);
                    *(__half2*)(Tsm + r*TSM_LD + h0) = __floats2half2_rn(v0, v1);
                }
            }
        }
        cp_commit_wait_all();
        __syncthreads();

        // ---- GEMM3, then LN directly from accumulators (residual from Asm) ----
        zero_acc(acc);
        gemm_tile(acc, aBaseT, bBase);

        float2* P2 = (float2*)(smem + OFF_P2);   // [2][96][4]
        #pragma unroll
        for (int mi = 0; mi < 2; mi++) {
            int rb = wm*32 + mi*16 + g;
            #pragma unroll
            for (int s = 0; s < 2; s++) {
                int r = rb + s*8;
                float psum = 0.0f, psq = 0.0f;
                #pragma unroll
                for (int j = 0; j < 4; j++) {
                    int h0 = wn*32 + j*8 + q*2;
                    float2 he = __half22float2(*(const __half2*)(Asm + r*ASM_LD + h0));
                    float x0 = acc[mi][j][2*s]   + GBEs[256 + h0]     + he.x;
                    float x1 = acc[mi][j][2*s+1] + GBEs[256 + h0 + 1] + he.y;
                    acc[mi][j][2*s] = x0; acc[mi][j][2*s+1] = x1;
                    psum += x0 + x1;
                    psq  += x0*x0 + x1*x1;
                }
                psum += __shfl_xor_sync(0xffffffffu, psum, 1);
                psq  += __shfl_xor_sync(0xffffffffu, psq, 1);
                psum += __shfl_xor_sync(0xffffffffu, psum, 2);
                psq  += __shfl_xor_sync(0xffffffffu, psq, 2);
                if (q == 0) P2[mi*384 + r*4 + wn] = make_float2(psum, psq);
            }
        }
        __syncthreads();
        #pragma unroll
        for (int mi = 0; mi < 2; mi++) {
            int rb = wm*32 + mi*16 + g;
            #pragma unroll
            for (int s = 0; s < 2; s++) {
                int r = rb + s*8;
                int nl = (r >= 48), k = r - nl*48;
                size_t eoff = (size_t)((node0 + nl)*KK + k) * HH;
                float2 p0 = P2[mi*384 + r*4 + 0];
                float2 p1 = P2[mi*384 + r*4 + 1];
                float2 p2 = P2[mi*384 + r*4 + 2];
                float2 p3 = P2[mi*384 + r*4 + 3];
                float sum = p0.x + p1.x + p2.x + p3.x;
                float sq  = p0.y + p1.y + p2.y + p3.y;
                float m   = sum * (1.0f/128.0f);
                float var = sq * (1.0f/128.0f) - m*m;
                float rs  = rsqrtf(var + 1e-5f);
                #pragma unroll
                for (int j = 0; j < 4; j++) {
                    int h0 = wn*32 + j*8 + q*2;
                    float o0 = (acc[mi][j][2*s]   - m)*rs*GBEs[h0]     + GBEs[128 + h0];
                    float o1 = (acc[mi][j][2*s+1] - m)*rs*GBEs[h0 + 1] + GBEs[128 + h0 + 1];
                    *(float2*)(out + eoff + h0) = make_float2(o0, o1);
                }
            }
        }
    }
}

// ---------------- K2: LN1 + FFN (wmma, 64 nodes/block) + LN2 + mask ----------------
#include <mma.h>
using namespace nvcuda;
using FragA = wmma::fragment<wmma::matrix_a, 16,16,16, __half, wmma::row_major>;
using FragB = wmma::fragment<wmma::matrix_b, 16,16,16, __half, wmma::row_major>;
using FragC = wmma::fragment<wmma::accumulator, 16,16,16, float>;

__global__ __launch_bounds__(256, 2)
void ffn_wmma_kernel(const float* __restrict__ hV, const float* __restrict__ dh,
                     const float* __restrict__ g1, const float* __restrict__ be1,
                     const float* __restrict__ g2, const float* __restrict__ be2,
                     const __half* __restrict__ Winh, const float* __restrict__ binf,
                     const __half* __restrict__ Wouth, const float* __restrict__ bout,
                     const float* __restrict__ mask_V, float* __restrict__ vln,
                     float* __restrict__ outV)
{
    extern __shared__ char smem[];
    __half* Vh  = (__half*)(smem + FFN_OFF_V);
    __half* Fsm = (__half*)(smem + FFN_OFF_F);
    __half* Wsm = (__half*)(smem + FFN_OFF_W);
    float*  Csm = (float*)(smem + FFN_OFF_C);

    const int tid = threadIdx.x;
    const int node0 = blockIdx.x * 64;
    const int wp = tid >> 5, lane = tid & 31;
    const int wm = wp & 3, wn = wp >> 2;

    for (int i = 0; i < 8; i++) {
        int nl = wp*8 + i, n = node0 + nl;
        float u[4]; float m = 0.0f;
        #pragma unroll
        for (int q = 0; q < 4; q++) {
            int h = lane + 32*q;
            u[q] = hV[(size_t)n*HH + h] + dh[(size_t)n*HH + h];
            m += u[q];
        }
        m = warp_sum(m) * (1.0f/128.0f);
        float var = 0.0f;
        #pragma unroll
        for (int q = 0; q < 4; q++) { float d = u[q]-m; var += d*d; }
        var = warp_sum(var) * (1.0f/128.0f);
        float rs = rsqrtf(var + 1e-5f);
        #pragma unroll
        for (int q = 0; q < 4; q++) {
            int h = lane + 32*q;
            float vl = (u[q]-m)*rs*g1[h] + be1[h];
            Vh[nl*136 + h] = __float2half(vl);
            vln[(size_t)n*HH + h] = vl;
        }
    }
    __syncthreads();

    FragC acc2[4];
    #pragma unroll
    for (int j = 0; j < 4; j++) wmma::fill_fragment(acc2[j], 0.0f);

    for (int jc = 0; jc < 4; jc++) {
        for (int idx = tid; idx < 2048; idx += 256) {
            int row = idx >> 4, c = idx & 15;
            cp16(Wsm + row*136 + c*8, Winh + (size_t)row*FFD + jc*128 + c*8);
        }
        cp_commit_wait_all();
        __syncthreads();
        FragC acc1[4];
        #pragma unroll
        for (int j = 0; j < 4; j++) wmma::fill_fragment(acc1[j], 0.0f);
        #pragma unroll
        for (int ks = 0; ks < 8; ks++) {
            FragA fa;
            wmma::load_matrix_sync(fa, Vh + (wm*16)*136 + ks*16, 136);
            #pragma unroll
            for (int j = 0; j < 4; j++) {
                FragB fb;
                wmma::load_matrix_sync(fb, Wsm + (ks*16)*136 + wn*64 + j*16, 136);
                wmma::mma_sync(acc1[j], fa, fb, acc1[j]);
            }
        }
        #pragma unroll
        for (int j = 0; j < 4; j++)
            wmma::store_matrix_sync(Csm + (wm*16)*FFN_CLD + wn*64 + j*16,
                                    acc1[j], FFN_CLD, wmma::mem_row_major);
        __syncthreads();
        for (int idx = tid; idx < 2048; idx += 256) {
            int row = idx >> 4, c = idx & 15;
            cp16(Wsm + row*136 + c*8, Wouth + (size_t)(jc*128 + row)*HH + c*8);
        }
        for (int idx = tid; idx < 64*128; idx += 256) {
            int r = idx >> 7, h = idx & 127;
            Fsm[r*136 + h] = __float2half(gelu_f(Csm[r*FFN_CLD + h] + binf[jc*128 + h]));
        }
        cp_commit_wait_all();
        __syncthreads();
        #pragma unroll
        for (int ks = 0; ks < 8; ks++) {
            FragA fa;
            wmma::load_matrix_sync(fa, Fsm + (wm*16)*136 + ks*16, 136);
            #pragma unroll
            for (int j = 0; j < 4; j++) {
                FragB fb;
                wmma::load_matrix_sync(fb, Wsm + (ks*16)*136 + wn*64 + j*16, 136);
                wmma::mma_sync(acc2[j], fa, fb, acc2[j]);
            }
        }
        __syncthreads();
    }
    #pragma unroll
    for (int j = 0; j < 4; j++)
        wmma::store_matrix_sync(Csm + (wm*16)*FFN_CLD + wn*64 + j*16,
                                acc2[j], FFN_CLD, wmma::mem_row_major);
    __syncthreads();

    for (int i = 0; i < 8; i++) {
        int nl = wp*8 + i, n = node0 + nl;
        float x[4]; float m = 0.0f;
        #pragma unroll
        for (int q = 0; q < 4; q++) {
            int h = lane + 32*q;
            x[q] = vln[(size_t)n*HH + h] + Csm[nl*FFN_CLD + h] + bout[h];
            m += x[q];
        }
        m = warp_sum(m) * (1.0f/128.0f);
        float var = 0.0f;
        #pragma unroll
        for (int q = 0; q < 4; q++) { float d = x[q]-m; var += d*d; }
        var = warp_sum(var) * (1.0f/128.0f);
        float rs = rsqrtf(var + 1e-5f);
        float mv = mask_V[n];
        #pragma unroll
        for (int q = 0; q < 4; q++) {
            int h = lane + 32*q;
            float o = ((x[q]-m)*rs*g2[h] + be2[h]) * mv;
            outV[(size_t)n*HH + h]  = o;
        }
    }
}

// ---------------- host ----------------
extern "C" void kernel_launch(void* const* d_in, const int* in_sizes, int n_in,
                              void* d_out, int out_size) {
    const float* h_V      = (const float*)d_in[0];
    const float* h_E      = (const float*)d_in[1];
    const float* mask_V   = (const float*)d_in[2];
    const float* mask_att = (const float*)d_in[3];
    const float* W1   = (const float*)d_in[4];
    const float* b1   = (const float*)d_in[5];
    const float* W2   = (const float*)d_in[6];
    const float* b2   = (const float*)d_in[7];
    const float* W3   = (const float*)d_in[8];
    const float* b3   = (const float*)d_in[9];
    const float* W11  = (const float*)d_in[10];
    const float* b11  = (const float*)d_in[11];
    const float* W12  = (const float*)d_in[12];
    const float* b12  = (const float*)d_in[13];
    const float* W13  = (const float*)d_in[14];
    const float* b13  = (const float*)d_in[15];
    const float* Win  = (const float*)d_in[16];
    const float* binf = (const float*)d_in[17];
    const float* Wout = (const float*)d_in[18];
    const float* bout = (const float*)d_in[19];
    const float* g1   = (const float*)d_in[20];
    const float* be1  = (const float*)d_in[21];
    const float* g2   = (const float*)d_in[22];
    const float* be2  = (const float*)d_in[23];
    const float* g3   = (const float*)d_in[24];
    const float* be3  = (const float*)d_in[25];
    const int*   E_idx = (const int*)d_in[26];

    float* outV = (float*)d_out;
    float* outE = outV + (size_t)NN*HH;

    cudaFuncSetAttribute(msg_kernel<true>,  cudaFuncAttributeMaxDynamicSharedMemorySize, SMEM_BYTES);
    cudaFuncSetAttribute(msg_kernel<false>, cudaFuncAttributeMaxDynamicSharedMemorySize, SMEM_BYTES);
    cudaFuncSetAttribute(ffn_wmma_kernel,   cudaFuncAttributeMaxDynamicSharedMemorySize, FFN_SMEM);

    __half *W1h, *W2h, *W3h, *W11h, *W12h, *W13h, *Winh, *Wouth, *hEh, *T3hp;
    float *dhp, *S1p, *vlnp;
    cudaGetSymbolAddress((void**)&W1h,  g_W1h);
    cudaGetSymbolAddress((void**)&W2h,  g_W2h);
    cudaGetSymbolAddress((void**)&W3h,  g_W3h);
    cudaGetSymbolAddress((void**)&W11h, g_W11h);
    cudaGetSymbolAddress((void**)&W12h, g_W12h);
    cudaGetSymbolAddress((void**)&W13h, g_W13h);
    cudaGetSymbolAddress((void**)&Winh, g_Winh);
    cudaGetSymbolAddress((void**)&Wouth,g_Wouth);
    cudaGetSymbolAddress((void**)&hEh,  g_hEh);
    cudaGetSymbolAddress((void**)&T3hp, g_T3h);
    cudaGetSymbolAddress((void**)&dhp,  g_dh);
    cudaGetSymbolAddress((void**)&S1p,  g_S1);
    cudaGetSymbolAddress((void**)&vlnp, g_vln);

    convert_kernel<<<CV_GRID, 512>>>(h_E, W1, W2, W3, W11, W12, W13, Win, Wout);

    s1t3_kernel<<<NN/8, 128>>>(h_V, W1, b1, S1p, T3hp);

    msg_kernel<true><<<NN/NPB, MSG_THREADS, SMEM_BYTES>>>(
        hEh, S1p, T3hp, W1h, W2h, W3h, b2, b3,
        E_idx, mask_att, g1, be1, dhp);

    ffn_wmma_kernel<<<NN/64, 256, FFN_SMEM>>>(h_V, dhp, g1, be1, g2, be2,
                                              Winh, binf, Wouth, bout, mask_V,
                                              vlnp, outV);

    s1t3_kernel<<<NN/8, 128>>>(outV, W11, b11, S1p, T3hp);

    msg_kernel<false><<<NN/NPB, MSG_THREADS, SMEM_BYTES>>>(
        hEh, S1p, T3hp, W11h, W12h, W13h, b12, b13,
        E_idx, nullptr, g3, be3, outE);
}